// round 6
// baseline (speedup 1.0000x reference)
#include <cuda_runtime.h>
#include <cstdint>

// LmulLinear: out[m,p] = sum_k bitcast_f32(bits(x[m,k]) + bits(w[p,k]) - OFFSET) + bias[p]
// M=256, K=512, P=512.
//
// R6: single-launch cross-CTA split-K x8 with fused deterministic "last CTA
//     reduces" fixup (counter + L2 scratch). 1024 CTAs x 256 thr -> ~14
//     warps/SMSP. f32x2 packed inner loop.

#define M_DIM 256
#define K_DIM 512
#define P_DIM 512
#define BM 32
#define BN 32
#define KSPLIT 8
#define KG (K_DIM / KSPLIT)     // 64 k per CTA
#define SROW (KG + 4)           // 68 words: conflict-free quarter-warp LDS.128
#define TILE_WORDS (BM * SROW)  // 2176 words
#define NGROUP ((M_DIM / BM) * (P_DIM / BN))  // 128 output blocks

__device__ float g_partial[KSPLIT * M_DIM * P_DIM];  // 4 MB scratch (L2-resident)
__device__ int   g_count[NGROUP];                     // zero-init; reset each run

// acc(f32x2) += ( f32(a+b0), f32(a+b1) )
#define LMAC(acc, a, b0, b1)                                                   \
    asm("{\n\t"                                                                \
        ".reg .b32 lo, hi;\n\t"                                                \
        ".reg .b64 t;\n\t"                                                     \
        "add.u32 lo, %1, %2;\n\t"                                              \
        "add.u32 hi, %1, %3;\n\t"                                              \
        "mov.b64 t, {lo, hi};\n\t"                                             \
        "add.rn.f32x2 %0, %0, t;\n\t"                                          \
        "}" : "+l"(acc) : "r"(a), "r"(b0), "r"(b1))

__global__ void __launch_bounds__(256)
lmul_fused_kernel(const float* __restrict__ x,
                  const float* __restrict__ w,
                  const float* __restrict__ bias,
                  float* __restrict__ out)
{
    constexpr uint32_t OFFSET = 1064828928u;  // 0x3F780000

    __shared__ uint32_t As[TILE_WORDS];   // [BM][SROW]
    __shared__ uint32_t Bs[TILE_WORDS];   // [BN][SROW], offset-folded
    __shared__ int s_last;

    const int tid = threadIdx.x;
    const int tx  = tid & 15;        // p cols: tx, tx+16
    const int ty  = tid >> 4;        // m rows: ty, ty+16
    const int m0  = blockIdx.y * BM;
    const int p0  = blockIdx.x * BN;
    const int ks  = blockIdx.z;
    const int kbase = ks * KG;
    const int gidx = blockIdx.y * (P_DIM / BN) + blockIdx.x;

    const uint32_t* __restrict__ xu = reinterpret_cast<const uint32_t*>(x);
    const uint32_t* __restrict__ wu = reinterpret_cast<const uint32_t*>(w);

    // ---- load tiles: 32 rows x 16 uint4 each; 2 uint4 per thread per tile ----
    #pragma unroll
    for (int i = 0; i < 2; i++) {
        int idx = tid + i * 256;        // 0..511
        int row = idx >> 4;             // 16 uint4 per row
        int c   = (idx & 15) * 4;
        uint4 va = *reinterpret_cast<const uint4*>(&xu[(m0 + row) * K_DIM + kbase + c]);
        *reinterpret_cast<uint4*>(&As[row * SROW + c]) = va;
        uint4 vb = *reinterpret_cast<const uint4*>(&wu[(p0 + row) * K_DIM + kbase + c]);
        vb.x -= OFFSET; vb.y -= OFFSET; vb.z -= OFFSET; vb.w -= OFFSET;
        *reinterpret_cast<uint4*>(&Bs[row * SROW + c]) = vb;
    }
    __syncthreads();

    // ---- 2x2 microtile (rows {ty,ty+16} x cols {tx,tx+16}), f32x2 accs ----
    const uint32_t* a0p = As + ty * SROW;
    const uint32_t* a1p = As + (ty + 16) * SROW;
    const uint32_t* b0p = Bs + tx * SROW;
    const uint32_t* b1p = Bs + (tx + 16) * SROW;

    uint64_t accA = 0ull;   // row ty    : (col tx, col tx+16)
    uint64_t accB = 0ull;   // row ty+16 : (col tx, col tx+16)

    #pragma unroll
    for (int j = 0; j < KG / 4; j++) {
        uint4 a0 = *reinterpret_cast<const uint4*>(a0p + 4 * j);
        uint4 a1 = *reinterpret_cast<const uint4*>(a1p + 4 * j);
        uint4 b0 = *reinterpret_cast<const uint4*>(b0p + 4 * j);
        uint4 b1 = *reinterpret_cast<const uint4*>(b1p + 4 * j);

        LMAC(accA, a0.x, b0.x, b1.x);  LMAC(accB, a1.x, b0.x, b1.x);
        LMAC(accA, a0.y, b0.y, b1.y);  LMAC(accB, a1.y, b0.y, b1.y);
        LMAC(accA, a0.z, b0.z, b1.z);  LMAC(accB, a1.z, b0.z, b1.z);
        LMAC(accA, a0.w, b0.w, b1.w);  LMAC(accB, a1.w, b0.w, b1.w);
    }

    // ---- publish partials to L2 scratch (skip L1) ----
    float* part = g_partial + ks * (M_DIM * P_DIM);
    {
        uint32_t lo, hi;
        asm("mov.b64 {%0, %1}, %2;" : "=r"(lo), "=r"(hi) : "l"(accA));
        __stcg(&part[(m0 + ty) * P_DIM + p0 + tx],      __uint_as_float(lo));
        __stcg(&part[(m0 + ty) * P_DIM + p0 + tx + 16], __uint_as_float(hi));
        asm("mov.b64 {%0, %1}, %2;" : "=r"(lo), "=r"(hi) : "l"(accB));
        __stcg(&part[(m0 + ty + 16) * P_DIM + p0 + tx],      __uint_as_float(lo));
        __stcg(&part[(m0 + ty + 16) * P_DIM + p0 + tx + 16], __uint_as_float(hi));
    }
    __threadfence();
    __syncthreads();

    // ---- last CTA of this output block reduces ----
    if (tid == 0) {
        int old = atomicAdd(&g_count[gidx], 1);
        s_last = (old == KSPLIT - 1);
    }
    __syncthreads();
    if (!s_last) return;
    __threadfence();  // acquire: make other CTAs' partials visible

    // 32x32 block = 256 float4; one float4 per thread.
    const int r  = tid >> 3;             // 0..31
    const int cg = (tid & 7) * 4;        // 0,4,...,28
    const int m  = m0 + r;
    const int p  = p0 + cg;
    const int off = m * P_DIM + p;

    float4 s = __ldcg(reinterpret_cast<const float4*>(g_partial + off));
    #pragma unroll
    for (int k = 1; k < KSPLIT; k++) {
        float4 v = __ldcg(reinterpret_cast<const float4*>(g_partial + k * (M_DIM * P_DIM) + off));
        s.x += v.x; s.y += v.y; s.z += v.z; s.w += v.w;
    }
    float4 b = *reinterpret_cast<const float4*>(bias + p);
    s.x += b.x; s.y += b.y; s.z += b.z; s.w += b.w;
    *reinterpret_cast<float4*>(out + off) = s;

    if (tid == 0) g_count[gidx] = 0;  // reset for next graph replay
}

extern "C" void kernel_launch(void* const* d_in, const int* in_sizes, int n_in,
                              void* d_out, int out_size)
{
    const float* x    = (const float*)d_in[0];   // (256, 512)
    const float* w    = (const float*)d_in[1];   // (512, 512)
    const float* bias = (const float*)d_in[2];   // (512,)
    float* out = (float*)d_out;                  // (256, 512)

    dim3 grid(P_DIM / BN, M_DIM / BM, KSPLIT);   // (16, 8, 8) = 1024 CTAs
    lmul_fused_kernel<<<grid, 256>>>(x, w, bias, out);
}

// round 7
// speedup vs baseline: 1.2500x; 1.2500x over previous
#include <cuda_runtime.h>
#include <cstdint>

// LmulLinear: out[m,p] = sum_k bitcast_f32(bits(x[m,k]) + bits(w[p,k]) - OFFSET) + bias[p]
// M=256, K=512, P=512.
//
// R7: GEMM split-K x4 (256 CTAs x 256 thr, BM=64 x BN=32, 4x2 microtile, scalar
//     IADD+FADD, software-pipelined LDS) + wide low-latency reduce kernel.

#define M_DIM 256
#define K_DIM 512
#define P_DIM 512
#define BM 64
#define BN 32
#define KSPLIT 4
#define KG (K_DIM / KSPLIT)        // 128 k per CTA
#define SROW (KG + 4)              // 132 words
#define A_WORDS (BM * SROW)        // 8448
#define B_WORDS (BN * SROW)        // 4224
#define SMEM_BYTES ((A_WORDS + B_WORDS) * 4)   // 50688 B

__device__ float g_partial[KSPLIT * M_DIM * P_DIM];   // 2 MB, L2-resident

static __device__ __forceinline__ float u2f(uint32_t u) { return __uint_as_float(u); }

extern __shared__ uint32_t smem[];

__global__ void __launch_bounds__(256)
lmul_partial_kernel(const float* __restrict__ x,
                    const float* __restrict__ w)
{
    constexpr uint32_t OFFSET = 1064828928u;  // 0x3F780000

    const int tid = threadIdx.x;
    const int tx  = tid & 15;          // p cols: tx, tx+16
    const int ty  = tid >> 4;          // m rows: ty, ty+16, ty+32, ty+48
    const int m0  = blockIdx.y * BM;
    const int p0  = blockIdx.x * BN;
    const int kbase = blockIdx.z * KG;

    uint32_t* As = smem;            // [BM][SROW]
    uint32_t* Bs = smem + A_WORDS;  // [BN][SROW], offset-folded

    const uint32_t* __restrict__ xu = reinterpret_cast<const uint32_t*>(x);
    const uint32_t* __restrict__ wu = reinterpret_cast<const uint32_t*>(w);

    // ---- load tiles: A = 64 rows x 32 uint4 (8/thread), B = 32 x 32 (4/thread) ----
    #pragma unroll
    for (int i = 0; i < 8; i++) {
        int idx = tid + i * 256;         // 0..2047
        int row = idx >> 5;
        int c   = (idx & 31) * 4;
        uint4 va = *reinterpret_cast<const uint4*>(&xu[(m0 + row) * K_DIM + kbase + c]);
        *reinterpret_cast<uint4*>(&As[row * SROW + c]) = va;
    }
    #pragma unroll
    for (int i = 0; i < 4; i++) {
        int idx = tid + i * 256;         // 0..1023
        int row = idx >> 5;
        int c   = (idx & 31) * 4;
        uint4 vb = *reinterpret_cast<const uint4*>(&wu[(p0 + row) * K_DIM + kbase + c]);
        vb.x -= OFFSET; vb.y -= OFFSET; vb.z -= OFFSET; vb.w -= OFFSET;
        *reinterpret_cast<uint4*>(&Bs[row * SROW + c]) = vb;
    }
    __syncthreads();

    // ---- 4x2 microtile, software-pipelined over 32 k-quads ----
    const uint32_t* a0p = As + (ty +  0) * SROW;
    const uint32_t* a1p = As + (ty + 16) * SROW;
    const uint32_t* a2p = As + (ty + 32) * SROW;
    const uint32_t* a3p = As + (ty + 48) * SROW;
    const uint32_t* b0p = Bs + tx * SROW;
    const uint32_t* b1p = Bs + (tx + 16) * SROW;

    float acc[8];
    #pragma unroll
    for (int r = 0; r < 8; r++) acc[r] = 0.f;

    // prologue loads
    uint4 a0 = *reinterpret_cast<const uint4*>(a0p);
    uint4 a1 = *reinterpret_cast<const uint4*>(a1p);
    uint4 a2 = *reinterpret_cast<const uint4*>(a2p);
    uint4 a3 = *reinterpret_cast<const uint4*>(a3p);
    uint4 b0 = *reinterpret_cast<const uint4*>(b0p);
    uint4 b1 = *reinterpret_cast<const uint4*>(b1p);

    #pragma unroll
    for (int j = 0; j < KG / 4; j++) {
        uint4 na0, na1, na2, na3, nb0, nb1;
        if (j + 1 < KG / 4) {
            na0 = *reinterpret_cast<const uint4*>(a0p + 4 * (j + 1));
            na1 = *reinterpret_cast<const uint4*>(a1p + 4 * (j + 1));
            na2 = *reinterpret_cast<const uint4*>(a2p + 4 * (j + 1));
            na3 = *reinterpret_cast<const uint4*>(a3p + 4 * (j + 1));
            nb0 = *reinterpret_cast<const uint4*>(b0p + 4 * (j + 1));
            nb1 = *reinterpret_cast<const uint4*>(b1p + 4 * (j + 1));
        }

        acc[0] += u2f(a0.x + b0.x); acc[1] += u2f(a0.x + b1.x);
        acc[2] += u2f(a1.x + b0.x); acc[3] += u2f(a1.x + b1.x);
        acc[4] += u2f(a2.x + b0.x); acc[5] += u2f(a2.x + b1.x);
        acc[6] += u2f(a3.x + b0.x); acc[7] += u2f(a3.x + b1.x);

        acc[0] += u2f(a0.y + b0.y); acc[1] += u2f(a0.y + b1.y);
        acc[2] += u2f(a1.y + b0.y); acc[3] += u2f(a1.y + b1.y);
        acc[4] += u2f(a2.y + b0.y); acc[5] += u2f(a2.y + b1.y);
        acc[6] += u2f(a3.y + b0.y); acc[7] += u2f(a3.y + b1.y);

        acc[0] += u2f(a0.z + b0.z); acc[1] += u2f(a0.z + b1.z);
        acc[2] += u2f(a1.z + b0.z); acc[3] += u2f(a1.z + b1.z);
        acc[4] += u2f(a2.z + b0.z); acc[5] += u2f(a2.z + b1.z);
        acc[6] += u2f(a3.z + b0.z); acc[7] += u2f(a3.z + b1.z);

        acc[0] += u2f(a0.w + b0.w); acc[1] += u2f(a0.w + b1.w);
        acc[2] += u2f(a1.w + b0.w); acc[3] += u2f(a1.w + b1.w);
        acc[4] += u2f(a2.w + b0.w); acc[5] += u2f(a2.w + b1.w);
        acc[6] += u2f(a3.w + b0.w); acc[7] += u2f(a3.w + b1.w);

        a0 = na0; a1 = na1; a2 = na2; a3 = na3; b0 = nb0; b1 = nb1;
    }

    // ---- write partials (coalesced per warp), skip L1 ----
    float* part = g_partial + blockIdx.z * (M_DIM * P_DIM);
    #pragma unroll
    for (int r = 0; r < 4; r++) {
        const int m = m0 + ty + 16 * r;
        __stcg(&part[m * P_DIM + p0 + tx],      acc[2 * r + 0]);
        __stcg(&part[m * P_DIM + p0 + tx + 16], acc[2 * r + 1]);
    }
}

__global__ void __launch_bounds__(128)
lmul_reduce_kernel(const float* __restrict__ bias,
                   float* __restrict__ out)
{
    // 32768 float4 outputs; 256 CTAs x 128 threads, one float4 each, MLP=5.
    const int idx4 = blockIdx.x * 128 + threadIdx.x;   // 0..32767
    const int base = idx4 * 4;
    const int p = base & (P_DIM - 1);

    float4 v0 = __ldcg(reinterpret_cast<const float4*>(g_partial + 0 * M_DIM * P_DIM + base));
    float4 v1 = __ldcg(reinterpret_cast<const float4*>(g_partial + 1 * M_DIM * P_DIM + base));
    float4 v2 = __ldcg(reinterpret_cast<const float4*>(g_partial + 2 * M_DIM * P_DIM + base));
    float4 v3 = __ldcg(reinterpret_cast<const float4*>(g_partial + 3 * M_DIM * P_DIM + base));
    float4 b  = __ldg(reinterpret_cast<const float4*>(bias + p));

    float4 r;
    r.x = ((v0.x + v1.x) + (v2.x + v3.x)) + b.x;
    r.y = ((v0.y + v1.y) + (v2.y + v3.y)) + b.y;
    r.z = ((v0.z + v1.z) + (v2.z + v3.z)) + b.z;
    r.w = ((v0.w + v1.w) + (v2.w + v3.w)) + b.w;

    *reinterpret_cast<float4*>(out + base) = r;
}

extern "C" void kernel_launch(void* const* d_in, const int* in_sizes, int n_in,
                              void* d_out, int out_size)
{
    const float* x    = (const float*)d_in[0];   // (256, 512)
    const float* w    = (const float*)d_in[1];   // (512, 512)
    const float* bias = (const float*)d_in[2];   // (512,)
    float* out = (float*)d_out;                  // (256, 512)

    cudaFuncSetAttribute(lmul_partial_kernel,
                         cudaFuncAttributeMaxDynamicSharedMemorySize, SMEM_BYTES);

    dim3 grid1(P_DIM / BN, M_DIM / BM, KSPLIT);  // (16, 4, 4) = 256 CTAs
    lmul_partial_kernel<<<grid1, 256, SMEM_BYTES>>>(x, w);

    dim3 grid2((M_DIM * P_DIM) / (128 * 4));     // 256 CTAs
    lmul_reduce_kernel<<<grid2, 128>>>(bias, out);
}

// round 8
// speedup vs baseline: 1.2531x; 1.0025x over previous
#include <cuda_runtime.h>
#include <cstdint>

// LmulLinear: out[m,p] = sum_k bitcast_f32(bits(x[m,k]) + bits(w[p,k]) - OFFSET) + bias[p]
// M=256, K=512, P=512.
//
// R8: deep-occupancy GEMM: 1024 CTAs x 128 thr (BM=32,BN=32,KSPLIT=8, 4x2 micro,
//     ~6.9 warps/SMSP, L0-resident loop) + fixed-order reduce kernel.

#define M_DIM 256
#define K_DIM 512
#define P_DIM 512
#define BM 32
#define BN 32
#define KSPLIT 8
#define KG (K_DIM / KSPLIT)        // 64 k per CTA
#define SROW (KG + 4)              // 68 words; 68/4=17 odd -> conflict-free LDS.128
#define TILE_WORDS (BM * SROW)     // 2176 words per tile

__device__ float g_partial[KSPLIT * M_DIM * P_DIM];   // 4 MB, L2-resident

static __device__ __forceinline__ float u2f(uint32_t u) { return __uint_as_float(u); }

__global__ void __launch_bounds__(128)
lmul_partial_kernel(const float* __restrict__ x,
                    const float* __restrict__ w)
{
    constexpr uint32_t OFFSET = 1064828928u;  // 0x3F780000

    __shared__ uint32_t As[TILE_WORDS];   // [BM][SROW]
    __shared__ uint32_t Bs[TILE_WORDS];   // [BN][SROW], offset-folded

    const int tid = threadIdx.x;
    const int tx  = tid & 15;          // p cols: tx, tx+16
    const int ty  = tid >> 4;          // m rows: ty, ty+8, ty+16, ty+24
    const int m0  = blockIdx.y * BM;
    const int p0  = blockIdx.x * BN;
    const int kbase = blockIdx.z * KG;

    const uint32_t* __restrict__ xu = reinterpret_cast<const uint32_t*>(x);
    const uint32_t* __restrict__ wu = reinterpret_cast<const uint32_t*>(w);

    // ---- load tiles: each 32 rows x 16 uint4 = 512 uint4; 4 per thread per tile ----
    #pragma unroll
    for (int i = 0; i < 4; i++) {
        int idx = tid + i * 128;         // 0..511
        int row = idx >> 4;
        int c   = (idx & 15) * 4;
        uint4 va = *reinterpret_cast<const uint4*>(&xu[(m0 + row) * K_DIM + kbase + c]);
        *reinterpret_cast<uint4*>(&As[row * SROW + c]) = va;
        uint4 vb = *reinterpret_cast<const uint4*>(&wu[(p0 + row) * K_DIM + kbase + c]);
        vb.x -= OFFSET; vb.y -= OFFSET; vb.z -= OFFSET; vb.w -= OFFSET;
        *reinterpret_cast<uint4*>(&Bs[row * SROW + c]) = vb;
    }
    __syncthreads();

    // ---- 4x2 microtile: rows {ty, ty+8, ty+16, ty+24}, cols {tx, tx+16} ----
    const uint32_t* a0p = As + (ty +  0) * SROW;
    const uint32_t* a1p = As + (ty +  8) * SROW;
    const uint32_t* a2p = As + (ty + 16) * SROW;
    const uint32_t* a3p = As + (ty + 24) * SROW;
    const uint32_t* b0p = Bs + tx * SROW;
    const uint32_t* b1p = Bs + (tx + 16) * SROW;

    float acc[8];
    #pragma unroll
    for (int r = 0; r < 8; r++) acc[r] = 0.f;

    #pragma unroll 4
    for (int j = 0; j < KG / 4; j++) {
        uint4 b0 = *reinterpret_cast<const uint4*>(b0p + 4 * j);
        uint4 b1 = *reinterpret_cast<const uint4*>(b1p + 4 * j);
        uint4 a0 = *reinterpret_cast<const uint4*>(a0p + 4 * j);
        uint4 a1 = *reinterpret_cast<const uint4*>(a1p + 4 * j);
        uint4 a2 = *reinterpret_cast<const uint4*>(a2p + 4 * j);
        uint4 a3 = *reinterpret_cast<const uint4*>(a3p + 4 * j);

        acc[0] += u2f(a0.x + b0.x); acc[1] += u2f(a0.x + b1.x);
        acc[2] += u2f(a1.x + b0.x); acc[3] += u2f(a1.x + b1.x);
        acc[4] += u2f(a2.x + b0.x); acc[5] += u2f(a2.x + b1.x);
        acc[6] += u2f(a3.x + b0.x); acc[7] += u2f(a3.x + b1.x);

        acc[0] += u2f(a0.y + b0.y); acc[1] += u2f(a0.y + b1.y);
        acc[2] += u2f(a1.y + b0.y); acc[3] += u2f(a1.y + b1.y);
        acc[4] += u2f(a2.y + b0.y); acc[5] += u2f(a2.y + b1.y);
        acc[6] += u2f(a3.y + b0.y); acc[7] += u2f(a3.y + b1.y);

        acc[0] += u2f(a0.z + b0.z); acc[1] += u2f(a0.z + b1.z);
        acc[2] += u2f(a1.z + b0.z); acc[3] += u2f(a1.z + b1.z);
        acc[4] += u2f(a2.z + b0.z); acc[5] += u2f(a2.z + b1.z);
        acc[6] += u2f(a3.z + b0.z); acc[7] += u2f(a3.z + b1.z);

        acc[0] += u2f(a0.w + b0.w); acc[1] += u2f(a0.w + b1.w);
        acc[2] += u2f(a1.w + b0.w); acc[3] += u2f(a1.w + b1.w);
        acc[4] += u2f(a2.w + b0.w); acc[5] += u2f(a2.w + b1.w);
        acc[6] += u2f(a3.w + b0.w); acc[7] += u2f(a3.w + b1.w);
    }

    // ---- write partials (coalesced), skip L1 ----
    float* part = g_partial + blockIdx.z * (M_DIM * P_DIM);
    #pragma unroll
    for (int r = 0; r < 4; r++) {
        const int m = m0 + ty + 8 * r;
        __stcg(&part[m * P_DIM + p0 + tx],      acc[2 * r + 0]);
        __stcg(&part[m * P_DIM + p0 + tx + 16], acc[2 * r + 1]);
    }
}

__global__ void __launch_bounds__(128)
lmul_reduce_kernel(const float* __restrict__ bias,
                   float* __restrict__ out)
{
    // 32768 float4 outputs; 256 CTAs x 128 threads, one float4 each, MLP=9.
    const int idx4 = blockIdx.x * 128 + threadIdx.x;   // 0..32767
    const int base = idx4 * 4;
    const int p = base & (P_DIM - 1);

    float4 v[KSPLIT];
    #pragma unroll
    for (int k = 0; k < KSPLIT; k++)
        v[k] = __ldcg(reinterpret_cast<const float4*>(g_partial + k * (M_DIM * P_DIM) + base));
    float4 b = __ldg(reinterpret_cast<const float4*>(bias + p));

    float4 r = v[0];
    #pragma unroll
    for (int k = 1; k < KSPLIT; k++) {
        r.x += v[k].x; r.y += v[k].y; r.z += v[k].z; r.w += v[k].w;
    }
    r.x += b.x; r.y += b.y; r.z += b.z; r.w += b.w;

    *reinterpret_cast<float4*>(out + base) = r;
}

extern "C" void kernel_launch(void* const* d_in, const int* in_sizes, int n_in,
                              void* d_out, int out_size)
{
    const float* x    = (const float*)d_in[0];   // (256, 512)
    const float* w    = (const float*)d_in[1];   // (512, 512)
    const float* bias = (const float*)d_in[2];   // (512,)
    float* out = (float*)d_out;                  // (256, 512)

    dim3 grid1(P_DIM / BN, M_DIM / BM, KSPLIT);  // (16, 8, 8) = 1024 CTAs
    lmul_partial_kernel<<<grid1, 128>>>(x, w);

    dim3 grid2((M_DIM * P_DIM) / (128 * 4));     // 256 CTAs
    lmul_reduce_kernel<<<grid2, 128>>>(bias, out);
}